// round 8
// baseline (speedup 1.0000x reference)
#include <cuda_runtime.h>
#include <stdint.h>

// ExtractSearchWindows: out[b,y,x, wy*7+wx, ty*7+tx] = Qpad[b][y+wy+ty][x+wx+tx]
// Qpad = zero-padded (pad=6) image, values = trunc(input) in [0,255). Output f32.
//
// 708 MB f32 stores -> pure store-BW problem. SINGLE launch; block (b,y,uslice)
// of 512 threads (4 blocks/SM = full 64 warp slots): builds 13x204 row table
// from the L2-resident input + 196 chunk descriptors in smem, then streams
// 196 float4 chunks x 12 x-groups as 196x6 32B units (u-major lane map keeps
// stores/desc reads coalesced). grid(384,49) -> W = 18816/592 = 31.78 waves
// -> 99.3% tail efficiency (vs 95.6% at 28 slices).

#define T_ROWS    13
#define T_COLS    208
#define NT        512
#define SLICE     196            // float4 chunks per block (49 * 196 = 9604)
#define NUNITS    (SLICE * 6)    // 1176 (u, xg-pair) units per block
#define ROW_ELEMS 460992         // 192 * 2401 floats per (b,y) row
#define XG_STRIDE 9604           // float4 stride between x-groups (38416/4)

__global__ __launch_bounds__(NT) void main_k(const float* __restrict__ in,
                                             float* __restrict__ out) {
    __shared__ float   Tsh[T_ROWS * T_COLS];
    __shared__ ushort4 Dsh[SLICE];

    int rowid = blockIdx.x;              // 0..383 = b*192 + y
    int usl   = blockIdx.y;              // 0..48
    int b   = rowid / 192;
    int y   = rowid - b * 192;
    int tid = threadIdx.x;
    int ubase = usl * SLICE;

    // ---- Prologue A: row table directly from input (pad=6, trunc-to-u8) ----
    // Tsh[r*208 + c] = Qpad[b][y+r][c] for r in [0,13), c in [0,204)
    const float* inb = in + (size_t)b * 192 * 192;
    for (int idx = tid; idx < T_ROWS * 204; idx += NT) {
        int r = idx / 204;
        int c = idx - r * 204;
        int gr = y + r - 6;              // global image row
        int gc = c - 6;                  // global image col
        float v = 0.0f;
        if ((unsigned)gr < 192u && (unsigned)gc < 192u)
            v = (float)__float2uint_rz(inb[gr * 192 + gc]);
        Tsh[r * T_COLS + c] = v;
    }

    // ---- Prologue B: per-chunk descriptors for this slice ----
    // Chunk u covers elements [4u,4u+4) of the 38416-elem 16-x region.
    // Element e: xi=e/2401, rr=e%2401 -> w=rr/49 (wy,wx), p=rr%49 (ty,tx);
    // smem offset = (wy+ty)*T_COLS + (xi+wx+tx); runtime adds 16*xg.
    if (tid < SLICE) {
        int u = ubase + tid;
        unsigned short off[4];
#pragma unroll
        for (int j = 0; j < 4; j++) {
            int e  = 4 * u + j;
            int xi = e / 2401;
            int rr = e - xi * 2401;
            int w  = rr / 49;
            int p  = rr - w * 49;
            int wy = w / 7, wx = w - wy * 7;
            int ty = p / 7, tx = p - ty * 7;
            off[j] = (unsigned short)((wy + ty) * T_COLS + (xi + wx + tx));
        }
        Dsh[tid] = make_ushort4(off[0], off[1], off[2], off[3]);
    }
    __syncthreads();

    // ---- Main store stream: units of 2 coalesced STG.128 (round-5 shape) ----
    float4* rowout4 = (float4*)(out + (size_t)rowid * ROW_ELEMS);

#pragma unroll 1
    for (int idx = tid; idx < NUNITS; idx += NT) {
        int xgp = idx / SLICE;           // 0..5 (pair of x-groups)
        int uu  = idx - xgp * SLICE;     // 0..195, u-major: lanes coalesced
        ushort4 d = Dsh[uu];
        float4* gp = rowout4 + (ubase + uu);

        int xg0 = 2 * xgp;
#pragma unroll
        for (int j = 0; j < 2; j++) {
            int st = (xg0 + j) * 16;     // +16 smem columns per x-group
            float4 v;
            v.x = Tsh[d.x + st];
            v.y = Tsh[d.y + st];
            v.z = Tsh[d.z + st];
            v.w = Tsh[d.w + st];
            __stcs(gp + (size_t)(xg0 + j) * XG_STRIDE, v);
        }
    }
}

// ---------------------------------------------------------------- launcher

extern "C" void kernel_launch(void* const* d_in, const int* in_sizes, int n_in,
                              void* d_out, int out_size) {
    const float* in = (const float*)d_in[0];
    // d_in[1] = search_range (fixed at 3: cv=7, offset=0 baked into descriptors)

    dim3 grid(384, 49);
    main_k<<<grid, NT>>>(in, (float*)d_out);
}

// round 9
// speedup vs baseline: 1.0593x; 1.0593x over previous
#include <cuda_runtime.h>
#include <stdint.h>

// ExtractSearchWindows: out[b,y,x, wy*7+wx, ty*7+tx] = Qpad[b][y+wy+ty][x+wx+tx]
// Qpad = zero-padded (pad=6) image, values = trunc(input) in [0,255). Output f32.
//
// 708 MB f32 stores -> pure store-BW problem. Persistent kernel: 592 blocks
// (exactly 4/SM), each looping over ~32 items; item = (row, slice of 196
// float4 chunks). Next item's 13x208 row table is prefetched via cp.async.cg
// into a double-buffered smem table DURING the current item's store loop
// (no whole-block prologue stall), descriptors double-buffered likewise.
// Store stream is the round-5 shape: 196x6 units of 2 coalesced STG.128.
// fill_k pre-truncates the padded image once so prefetch is a raw 16B copy.

#define T_ROWS    13
#define T_COLS    208
#define NT        512
#define SLICE     196            // float4 chunks per item (49 * 196 = 9604)
#define NSLICES   49
#define NITEMS    (384 * NSLICES)  // 18816
#define NBLK      592            // 148 SMs * 4 blocks
#define NUNITS    (SLICE * 6)    // 1176 (u, xg-pair) units per item
#define ROW_ELEMS 460992         // 192 * 2401 floats per (b,y) row
#define XG_STRIDE 9604           // float4 stride between x-groups (38416/4)
#define GP_ROWS   204
#define GP_PITCH  208

__device__ __align__(16) float g_padf[2][GP_ROWS][GP_PITCH];

// ---- prep: padded + truncated image, once (tiny) ----
__global__ void fill_k(const float* __restrict__ in) {
    int i = blockIdx.x * blockDim.x + threadIdx.x;   // 2*204*208 = 84864
    if (i >= 2 * GP_ROWS * GP_PITCH) return;
    int b   = i / (GP_ROWS * GP_PITCH);
    int rem = i - b * (GP_ROWS * GP_PITCH);
    int r   = rem / GP_PITCH;
    int c   = rem - r * GP_PITCH;
    float v = 0.0f;
    if (r >= 6 && r < 198 && c >= 6 && c < 198)
        v = (float)__float2uint_rz(in[(b * 192 + (r - 6)) * 192 + (c - 6)]);
    g_padf[b][r][c] = v;
}

// ---- helpers ----
__device__ __forceinline__ void cpa16(uint32_t dst, const void* src) {
    asm volatile("cp.async.cg.shared.global [%0], [%1], 16;\n"
                 :: "r"(dst), "l"(src) : "memory");
}
__device__ __forceinline__ void cpa_commit() {
    asm volatile("cp.async.commit_group;\n" ::: "memory");
}
__device__ __forceinline__ void cpa_wait0() {
    asm volatile("cp.async.wait_group 0;\n" ::: "memory");
}

// Prefetch 13x208-float row table for image row (b,y): 13 rows x 52 float4.
__device__ __forceinline__ void prefetch_table(uint32_t sbase, int b, int y, int tid) {
    const float4* src = (const float4*)&g_padf[b][y][0];   // pitch 52 float4
    for (int idx = tid; idx < T_ROWS * 52; idx += NT) {
        int r  = idx / 52;
        int c4 = idx - r * 52;
        cpa16(sbase + (uint32_t)(r * T_COLS + c4 * 4) * 4, (const void*)(src + r * 52 + c4));
    }
}

// Chunk u covers elements [4u,4u+4) of the 38416-elem 16-x region.
// Element e: xi=e/2401, rr=e%2401 -> w=rr/49 (wy,wx), p=rr%49 (ty,tx);
// smem offset = (wy+ty)*T_COLS + (xi+wx+tx); runtime adds 16*xg.
__device__ __forceinline__ ushort4 compute_desc(int u) {
    unsigned short off[4];
#pragma unroll
    for (int j = 0; j < 4; j++) {
        int e  = 4 * u + j;
        int xi = e / 2401;
        int rr = e - xi * 2401;
        int w  = rr / 49;
        int p  = rr - w * 49;
        int wy = w / 7, wx = w - wy * 7;
        int ty = p / 7, tx = p - ty * 7;
        off[j] = (unsigned short)((wy + ty) * T_COLS + (xi + wx + tx));
    }
    return make_ushort4(off[0], off[1], off[2], off[3]);
}

// ---- main persistent kernel ----
__global__ __launch_bounds__(NT, 4) void main_k(float* __restrict__ out) {
    __shared__ float   Tsh[2][T_ROWS * T_COLS];
    __shared__ ushort4 Dsh[2][SLICE];

    int bid = blockIdx.x;
    int tid = threadIdx.x;
    uint32_t tb[2];
    tb[0] = (uint32_t)__cvta_generic_to_shared(&Tsh[0][0]);
    tb[1] = (uint32_t)__cvta_generic_to_shared(&Tsh[1][0]);

    // Prime item 0 (i = bid < 592 always valid)
    {
        int i   = bid;
        int row = i % 384;
        int b   = row / 192, y = row - b * 192;
        prefetch_table(tb[0], b, y, tid);
        cpa_commit();
        if (tid < SLICE) {
            int sl = i / 384;
            Dsh[0][tid] = compute_desc(sl * SLICE + tid);
        }
        cpa_wait0();
    }
    __syncthreads();

#pragma unroll 1
    for (int k = 0;; k++) {
        int i = k * NBLK + bid;
        if (i >= NITEMS) break;
        int cur   = k & 1;
        int inext = i + NBLK;

        // Issue next item's table prefetch + descriptors (other buffers)
        if (inext < NITEMS) {
            int rown = inext % 384;
            int bn = rown / 192, yn = rown - bn * 192;
            prefetch_table(tb[cur ^ 1], bn, yn, tid);
        }
        cpa_commit();
        if (inext < NITEMS && tid < SLICE) {
            int sln = inext / 384;
            Dsh[cur ^ 1][tid] = compute_desc(sln * SLICE + tid);
        }

        // Store stream for current item (round-5 shape)
        int row   = i % 384;
        int sl    = i / 384;
        int ubase = sl * SLICE;
        const float* T = Tsh[cur];
        float4* rowout4 = (float4*)(out + (size_t)row * ROW_ELEMS);

#pragma unroll 1
        for (int idx = tid; idx < NUNITS; idx += NT) {
            int xgp = idx / SLICE;       // 0..5 (pair of x-groups)
            int uu  = idx - xgp * SLICE; // 0..195, u-major: lanes coalesced
            ushort4 d = Dsh[cur][uu];
            float4* gp = rowout4 + (ubase + uu);
            int xg0 = 2 * xgp;
#pragma unroll
            for (int j = 0; j < 2; j++) {
                int st = (xg0 + j) * 16; // +16 smem columns per x-group
                float4 v;
                v.x = T[d.x + st];
                v.y = T[d.y + st];
                v.z = T[d.z + st];
                v.w = T[d.w + st];
                __stcs(gp + (size_t)(xg0 + j) * XG_STRIDE, v);
            }
        }

        cpa_wait0();
        __syncthreads();
    }
}

// ---------------------------------------------------------------- launcher

extern "C" void kernel_launch(void* const* d_in, const int* in_sizes, int n_in,
                              void* d_out, int out_size) {
    const float* in = (const float*)d_in[0];
    // d_in[1] = search_range (fixed at 3: cv=7, offset=0 baked into descriptors)

    fill_k<<<(2 * GP_ROWS * GP_PITCH + 1023) / 1024, 1024>>>(in);
    main_k<<<NBLK, NT>>>((float*)d_out);
}

// round 10
// speedup vs baseline: 1.2098x; 1.1421x over previous
#include <cuda_runtime.h>
#include <stdint.h>

// ExtractSearchWindows: out[b,y,x, wy*7+wx, ty*7+tx] = Qpad[b][y+wy+ty][x+wx+tx]
// Qpad = zero-padded (pad=6) image, values = trunc(input) in [0,255). Output f32.
//
// 708 MB f32 stores -> pure store-BW problem. SINGLE launch; block (b,y,uslice)
// of 512 threads (4 blocks/SM = full 64 warp slots): builds a 13x208 row table
// (column-shifted by +2 so interior loads/stores are float4-aligned: table col
// t = image col + 8) + 343 chunk descriptors in smem, then streams 343 float4
// chunks x 12 x-groups as 343x6 32B units (u-major lane map keeps stores and
// descriptor reads coalesced). grid(384,28) -> W = 10752/592 = 18.16 waves
// -> 95.6% tail efficiency.  [Round-5 store shape, vectorized prologue.]

#define T_ROWS    13
#define T_COLS    208
#define NT        512
#define SLICE     343            // float4 chunks per block (28 * 343 = 9604)
#define NUNITS    (SLICE * 6)    // 2058 (u, xg-pair) units per block
#define ROW_ELEMS 460992         // 192 * 2401 floats per (b,y) row
#define XG_STRIDE 9604           // float4 stride between x-groups (38416/4)

__global__ __launch_bounds__(NT) void main_k(const float* __restrict__ in,
                                             float* __restrict__ out) {
    __shared__ float   Tsh[T_ROWS * T_COLS];
    __shared__ ushort4 Dsh[SLICE];

    int rowid = blockIdx.x;              // 0..383 = b*192 + y
    int usl   = blockIdx.y;              // 0..27
    int b   = rowid / 192;
    int y   = rowid - b * 192;
    int tid = threadIdx.x;
    int ubase = usl * SLICE;

    // ---- Prologue A (vectorized): row table, col-shifted layout ----
    // Tsh[r*208 + t] = Qpad[b][y+r][t-2] for t in [0,208); Qpad col = gc+6,
    // so t = gc + 8: interior image cols gc in [0,192) sit at t in [8,200),
    // 16B-aligned in both gmem and smem. 13 x 52 float4 units, 1.32/thread.
    const float* inb = in + (size_t)b * 192 * 192;
    for (int idx = tid; idx < T_ROWS * 52; idx += NT) {
        int r   = idx / 52;
        int t4  = idx - r * 52;          // float4 column 0..51
        int gr  = y + r - 6;             // global image row
        int gc0 = t4 * 4 - 8;            // global image col of lane 0
        float4 v = make_float4(0.f, 0.f, 0.f, 0.f);
        if ((unsigned)gr < 192u && (unsigned)gc0 < 192u) {
            float4 w = *(const float4*)(inb + gr * 192 + gc0);
            v.x = (float)__float2uint_rz(w.x);
            v.y = (float)__float2uint_rz(w.y);
            v.z = (float)__float2uint_rz(w.z);
            v.w = (float)__float2uint_rz(w.w);
        }
        *(float4*)&Tsh[r * T_COLS + t4 * 4] = v;
    }

    // ---- Prologue B: per-chunk descriptors for this slice ----
    // Chunk u covers elements [4u,4u+4) of the 38416-elem 16-x region.
    // Element e: xi=e/2401, rr=e%2401 -> w=rr/49 (wy,wx), p=rr%49 (ty,tx);
    // smem offset = (wy+ty)*T_COLS + (xi+wx+tx) + 2 (column shift);
    // runtime adds 16*xg.
    if (tid < SLICE) {
        int u = ubase + tid;
        unsigned short off[4];
#pragma unroll
        for (int j = 0; j < 4; j++) {
            int e  = 4 * u + j;
            int xi = e / 2401;
            int rr = e - xi * 2401;
            int w  = rr / 49;
            int p  = rr - w * 49;
            int wy = w / 7, wx = w - wy * 7;
            int ty = p / 7, tx = p - ty * 7;
            off[j] = (unsigned short)((wy + ty) * T_COLS + (xi + wx + tx) + 2);
        }
        Dsh[tid] = make_ushort4(off[0], off[1], off[2], off[3]);
    }
    __syncthreads();

    // ---- Main store stream: units of 2 coalesced STG.128 (round-5 shape) ----
    float4* rowout4 = (float4*)(out + (size_t)rowid * ROW_ELEMS);

#pragma unroll 1
    for (int idx = tid; idx < NUNITS; idx += NT) {
        int xgp = idx / SLICE;           // 0..5 (pair of x-groups)
        int uu  = idx - xgp * SLICE;     // 0..342, u-major: lanes coalesced
        ushort4 d = Dsh[uu];
        float4* gp = rowout4 + (ubase + uu);

        int xg0 = 2 * xgp;
#pragma unroll
        for (int j = 0; j < 2; j++) {
            int st = (xg0 + j) * 16;     // +16 smem columns per x-group
            float4 v;
            v.x = Tsh[d.x + st];
            v.y = Tsh[d.y + st];
            v.z = Tsh[d.z + st];
            v.w = Tsh[d.w + st];
            __stcs(gp + (size_t)(xg0 + j) * XG_STRIDE, v);
        }
    }
}

// ---------------------------------------------------------------- launcher

extern "C" void kernel_launch(void* const* d_in, const int* in_sizes, int n_in,
                              void* d_out, int out_size) {
    const float* in = (const float*)d_in[0];
    // d_in[1] = search_range (fixed at 3: cv=7, offset=0 baked into descriptors)

    dim3 grid(384, 28);
    main_k<<<grid, NT>>>(in, (float*)d_out);
}

// round 11
// speedup vs baseline: 1.2613x; 1.0426x over previous
#include <cuda_runtime.h>
#include <stdint.h>

// ExtractSearchWindows: out[b,y,x, wy*7+wx, ty*7+tx] = Qpad[b][y+wy+ty][x+wx+tx]
// Qpad = zero-padded (pad=6) image, values = trunc(input) in [0,255). Output f32.
//
// 708 MB f32 stores -> pure store-BW problem. SINGLE launch; block (b,y,uslice)
// of 512 threads (4 blocks/SM = full 64 warp slots): builds a 13x208 row table
// (column-shifted +2 so interior loads/stores are float4-aligned) + up to 260
// chunk descriptors in smem, then streams the slice's float4 chunks x 12
// x-groups as 32B units of 2 STG.128 (u-major lane map keeps stores coalesced).
// grid(384,37) -> W = 14208/592 = 24.00 waves EXACTLY -> no wave-quantization
// tail. Last slice (244 of 260 chunks) handled by a warp-uniform guard.

#define T_ROWS    13
#define T_COLS    208
#define NT        512
#define SLICE     260            // chunks per slice; 37*260 = 9620 >= 9604
#define NCHUNKS   9604           // float4 chunks per 38416-elem (16-x) region
#define NUNITS    (SLICE * 6)    // 1560 (u, xg-pair) units per block
#define ROW_ELEMS 460992         // 192 * 2401 floats per (b,y) row
#define XG_STRIDE 9604           // float4 stride between x-groups (38416/4)

__global__ __launch_bounds__(NT) void main_k(const float* __restrict__ in,
                                             float* __restrict__ out) {
    __shared__ float   Tsh[T_ROWS * T_COLS];
    __shared__ ushort4 Dsh[SLICE];

    int rowid = blockIdx.x;              // 0..383 = b*192 + y
    int usl   = blockIdx.y;              // 0..36
    int b   = rowid / 192;
    int y   = rowid - b * 192;
    int tid = threadIdx.x;
    int ubase = usl * SLICE;

    // ---- Prologue A (vectorized): row table, col-shifted layout ----
    // Tsh[r*208 + t] = Qpad[b][y+r][t-2]; Qpad col = gc+6, so t = gc+8:
    // interior cols gc in [0,192) sit at t in [8,200), 16B-aligned in both
    // gmem and smem. 13 x 52 float4 units, 1.32/thread, one L2 round.
    const float* inb = in + (size_t)b * 192 * 192;
    for (int idx = tid; idx < T_ROWS * 52; idx += NT) {
        int r   = idx / 52;
        int t4  = idx - r * 52;          // float4 column 0..51
        int gr  = y + r - 6;             // global image row
        int gc0 = t4 * 4 - 8;            // global image col of lane 0
        float4 v = make_float4(0.f, 0.f, 0.f, 0.f);
        if ((unsigned)gr < 192u && (unsigned)gc0 < 192u) {
            float4 w = *(const float4*)(inb + gr * 192 + gc0);
            v.x = (float)__float2uint_rz(w.x);
            v.y = (float)__float2uint_rz(w.y);
            v.z = (float)__float2uint_rz(w.z);
            v.w = (float)__float2uint_rz(w.w);
        }
        *(float4*)&Tsh[r * T_COLS + t4 * 4] = v;
    }

    // ---- Prologue B: per-chunk descriptors for this slice ----
    // Chunk u covers elements [4u,4u+4) of the 38416-elem 16-x region.
    // Element e: xi=e/2401, rr=e%2401 -> w=rr/49 (wy,wx), p=rr%49 (ty,tx);
    // smem offset = (wy+ty)*T_COLS + (xi+wx+tx) + 2 (column shift);
    // runtime adds 16*xg. Chunks past NCHUNKS are clamped (stores guarded).
    if (tid < SLICE) {
        int u = ubase + tid;
        if (u >= NCHUNKS) u = NCHUNKS - 1;
        unsigned short off[4];
#pragma unroll
        for (int j = 0; j < 4; j++) {
            int e  = 4 * u + j;
            int xi = e / 2401;
            int rr = e - xi * 2401;
            int w  = rr / 49;
            int p  = rr - w * 49;
            int wy = w / 7, wx = w - wy * 7;
            int ty = p / 7, tx = p - ty * 7;
            off[j] = (unsigned short)((wy + ty) * T_COLS + (xi + wx + tx) + 2);
        }
        Dsh[tid] = make_ushort4(off[0], off[1], off[2], off[3]);
    }
    __syncthreads();

    // ---- Main store stream: units of 2 coalesced STG.128 ----
    float4* rowout4 = (float4*)(out + (size_t)rowid * ROW_ELEMS);

#pragma unroll 1
    for (int idx = tid; idx < NUNITS; idx += NT) {
        int xgp = idx / SLICE;           // 0..5 (pair of x-groups)
        int uu  = idx - xgp * SLICE;     // 0..259, u-major: lanes coalesced
        int u   = ubase + uu;
        if (u < NCHUNKS) {               // warp-uniform except at slice edge
            ushort4 d = Dsh[uu];
            float4* gp = rowout4 + u;

            int xg0 = 2 * xgp;
#pragma unroll
            for (int j = 0; j < 2; j++) {
                int st = (xg0 + j) * 16; // +16 smem columns per x-group
                float4 v;
                v.x = Tsh[d.x + st];
                v.y = Tsh[d.y + st];
                v.z = Tsh[d.z + st];
                v.w = Tsh[d.w + st];
                __stcs(gp + (size_t)(xg0 + j) * XG_STRIDE, v);
            }
        }
    }
}

// ---------------------------------------------------------------- launcher

extern "C" void kernel_launch(void* const* d_in, const int* in_sizes, int n_in,
                              void* d_out, int out_size) {
    const float* in = (const float*)d_in[0];
    // d_in[1] = search_range (fixed at 3: cv=7, offset=0 baked into descriptors)

    dim3 grid(384, 37);
    main_k<<<grid, NT>>>(in, (float*)d_out);
}

// round 12
// speedup vs baseline: 1.3122x; 1.0403x over previous
#include <cuda_runtime.h>
#include <stdint.h>

// ExtractSearchWindows: out[b,y,x, wy*7+wx, ty*7+tx] = Qpad[b][y+wy+ty][x+wx+tx]
// Qpad = zero-padded (pad=6) image, values = trunc(input) in [0,255). Output f32.
//
// 708 MB f32 stores -> pure store-BW problem. SINGLE launch; block (slice,row)
// of 512 threads (4 blocks/SM = full 64 warp slots): builds a 13x208 row table
// (column-shifted +2 so interior loads/stores are float4-aligned) + up to 260
// chunk descriptors in smem, then streams the slice's float4 chunks x 12
// x-groups as 32B units of 2 STG.128 (u-major lane map keeps stores coalesced).
// grid(37,384): slice varies fastest -> each 592-block wave covers 16 FULL
// consecutive rows (~28 MB contiguous output) for DRAM page locality, and
// W = 14208/592 = 24.00 waves exactly (no wave-quantization tail).

#define T_ROWS    13
#define T_COLS    208
#define NT        512
#define SLICE     260            // chunks per slice; 37*260 = 9620 >= 9604
#define NCHUNKS   9604           // float4 chunks per 38416-elem (16-x) region
#define NUNITS    (SLICE * 6)    // 1560 (u, xg-pair) units per block
#define ROW_ELEMS 460992         // 192 * 2401 floats per (b,y) row
#define XG_STRIDE 9604           // float4 stride between x-groups (38416/4)

__global__ __launch_bounds__(NT) void main_k(const float* __restrict__ in,
                                             float* __restrict__ out) {
    __shared__ float   Tsh[T_ROWS * T_COLS];
    __shared__ ushort4 Dsh[SLICE];

    int usl   = blockIdx.x;              // 0..36  (fastest-varying)
    int rowid = blockIdx.y;              // 0..383 = b*192 + y
    int b   = rowid / 192;
    int y   = rowid - b * 192;
    int tid = threadIdx.x;
    int ubase = usl * SLICE;

    // ---- Prologue A (vectorized): row table, col-shifted layout ----
    // Tsh[r*208 + t] = Qpad[b][y+r][t-2]; Qpad col = gc+6, so t = gc+8:
    // interior cols gc in [0,192) sit at t in [8,200), 16B-aligned in both
    // gmem and smem. 13 x 52 float4 units, 1.32/thread, one L2 round.
    const float* inb = in + (size_t)b * 192 * 192;
    for (int idx = tid; idx < T_ROWS * 52; idx += NT) {
        int r   = idx / 52;
        int t4  = idx - r * 52;          // float4 column 0..51
        int gr  = y + r - 6;             // global image row
        int gc0 = t4 * 4 - 8;            // global image col of lane 0
        float4 v = make_float4(0.f, 0.f, 0.f, 0.f);
        if ((unsigned)gr < 192u && (unsigned)gc0 < 192u) {
            float4 w = *(const float4*)(inb + gr * 192 + gc0);
            v.x = (float)__float2uint_rz(w.x);
            v.y = (float)__float2uint_rz(w.y);
            v.z = (float)__float2uint_rz(w.z);
            v.w = (float)__float2uint_rz(w.w);
        }
        *(float4*)&Tsh[r * T_COLS + t4 * 4] = v;
    }

    // ---- Prologue B: per-chunk descriptors for this slice ----
    // Chunk u covers elements [4u,4u+4) of the 38416-elem 16-x region.
    // Element e: xi=e/2401, rr=e%2401 -> w=rr/49 (wy,wx), p=rr%49 (ty,tx);
    // smem offset = (wy+ty)*T_COLS + (xi+wx+tx) + 2 (column shift);
    // runtime adds 16*xg. Chunks past NCHUNKS are clamped (stores guarded).
    if (tid < SLICE) {
        int u = ubase + tid;
        if (u >= NCHUNKS) u = NCHUNKS - 1;
        unsigned short off[4];
#pragma unroll
        for (int j = 0; j < 4; j++) {
            int e  = 4 * u + j;
            int xi = e / 2401;
            int rr = e - xi * 2401;
            int w  = rr / 49;
            int p  = rr - w * 49;
            int wy = w / 7, wx = w - wy * 7;
            int ty = p / 7, tx = p - ty * 7;
            off[j] = (unsigned short)((wy + ty) * T_COLS + (xi + wx + tx) + 2);
        }
        Dsh[tid] = make_ushort4(off[0], off[1], off[2], off[3]);
    }
    __syncthreads();

    // ---- Main store stream: units of 2 coalesced STG.128 ----
    float4* rowout4 = (float4*)(out + (size_t)rowid * ROW_ELEMS);

#pragma unroll 1
    for (int idx = tid; idx < NUNITS; idx += NT) {
        int xgp = idx / SLICE;           // 0..5 (pair of x-groups)
        int uu  = idx - xgp * SLICE;     // 0..259, u-major: lanes coalesced
        int u   = ubase + uu;
        if (u < NCHUNKS) {               // warp-uniform except at slice edge
            ushort4 d = Dsh[uu];
            float4* gp = rowout4 + u;

            int xg0 = 2 * xgp;
#pragma unroll
            for (int j = 0; j < 2; j++) {
                int st = (xg0 + j) * 16; // +16 smem columns per x-group
                float4 v;
                v.x = Tsh[d.x + st];
                v.y = Tsh[d.y + st];
                v.z = Tsh[d.z + st];
                v.w = Tsh[d.w + st];
                __stcs(gp + (size_t)(xg0 + j) * XG_STRIDE, v);
            }
        }
    }
}

// ---------------------------------------------------------------- launcher

extern "C" void kernel_launch(void* const* d_in, const int* in_sizes, int n_in,
                              void* d_out, int out_size) {
    const float* in = (const float*)d_in[0];
    // d_in[1] = search_range (fixed at 3: cv=7, offset=0 baked into descriptors)

    dim3 grid(37, 384);                  // x=slice fastest -> waves = 16 full rows
    main_k<<<grid, NT>>>(in, (float*)d_out);
}